// round 7
// baseline (speedup 1.0000x reference)
#include <cuda_runtime.h>
#include <cstdint>

#define NROWS 65536
#define DDIM 512
#define NUM_LABELS 512
#define NUM_DEMOG 4
#define NGROUP (NUM_LABELS * NUM_DEMOG)

#define GRID_STREAM 444          /* 148 SMs x 3 CTAs: one wave guaranteed */
#define TS 256                   /* threads per stream CTA */
#define CHUNK 148                /* rows per CTA (444*148 = 65712 >= 65536) */
#define BR 8                     /* rows per batch */
#define NB 4                     /* ring depth in batches */
#define CHUNK_PAD 152            /* ceil(148/8)*8 */
#define NBATCH 19                /* CHUNK_PAD / BR */
#define ROWB 2048                /* bytes per row */

// -------- scratch (device globals; no allocation allowed) --------
__device__ int    g_cnt[NGROUP];
__device__ int    g_off[NGROUP + 1];
__device__ int    g_cursor[NGROUP];
__device__ int    g_sorted[NROWS];
__device__ int    g_seg_sorted[NROWS];
__device__ float4 g_sums4[NGROUP * (DDIM / 4)];   // 4 MB group vector sums
__device__ float  g_ssq[NGROUP];
__device__ double g_gm[NGROUP];
__device__ int    g_is64;
__device__ int    g_hist_done;
__device__ volatile int g_prep_flag;
__device__ int    g_stream_done;
__device__ int    g_fin_done;

// ========== k_init: single-wave grid-stride zero + dtype detect ==========
__global__ void __launch_bounds__(512) k_init(const int* labels_raw) {
    int i = blockIdx.x * 512 + threadIdx.x;       // 512 x 512 = 262144
    g_sums4[i] = make_float4(0.f, 0.f, 0.f, 0.f); // exactly NGROUP*128 elems
    if (i < NGROUP) { g_cnt[i] = 0; g_ssq[i] = 0.f; }
    if (i == 0) {
        int nz = 0;
        for (int k = 1; k < 64; k += 2) nz += (labels_raw[k] != 0);
        g_is64 = (nz == 0) ? 1 : 0;
        g_hist_done = 0;
        g_prep_flag = 0;
        g_stream_done = 0;
        g_fin_done = 0;
    }
}

__device__ __forceinline__ int load_idx_val(const void* p, int i, int is64) {
    if (is64) return (int)((const long long*)p)[i];
    return ((const int*)p)[i];
}

// ===== k_prep: hist -> last-CTA scan -> grid sync -> scatter (seg in regs) =====
// 64 CTAs x 1024 threads: one CTA per SM, single wave => spin is safe.
__global__ void __launch_bounds__(1024) k_prep(const void* labels, const void* demog) {
    int i = blockIdx.x * 1024 + threadIdx.x;      // 64 x 1024 = 65536 exactly
    int t = threadIdx.x;
    int is64 = g_is64;
    int lab = load_idx_val(labels, i, is64);
    int dem = load_idx_val(demog, i, is64);
    int seg = dem * NUM_LABELS + lab;
    atomicAdd(&g_cnt[seg], 1);

    __shared__ int s_last;
    __threadfence();
    __syncthreads();
    if (t == 0)
        s_last = (atomicAdd(&g_hist_done, 1) == gridDim.x - 1) ? 1 : 0;
    __syncthreads();

    if (s_last) {
        __threadfence();   // acquire: all g_cnt visible
        int lane = t & 31, warp = t >> 5;
        int a = g_cnt[2 * t];
        int b = g_cnt[2 * t + 1];
        int pair = a + b;
        int v = pair;
        #pragma unroll
        for (int d = 1; d < 32; d <<= 1) {
            int u = __shfl_up_sync(0xffffffffu, v, d);
            if (lane >= d) v += u;
        }
        __shared__ int wsum[32];
        if (lane == 31) wsum[warp] = v;
        __syncthreads();
        if (warp == 0) {
            int w = wsum[lane];
            int x = w;
            #pragma unroll
            for (int d = 1; d < 32; d <<= 1) {
                int u = __shfl_up_sync(0xffffffffu, x, d);
                if (lane >= d) x += u;
            }
            wsum[lane] = x - w;
        }
        __syncthreads();
        int incl = v + wsum[warp];
        int excl = incl - pair;
        g_off[2 * t]        = excl;
        g_off[2 * t + 1]    = excl + a;
        g_cursor[2 * t]     = excl;
        g_cursor[2 * t + 1] = excl + a;
        if (t == 1023) g_off[2048] = incl;
        __threadfence();
        __syncthreads();
        if (t == 0) g_prep_flag = 1;
    } else {
        if (t == 0) { while (g_prep_flag == 0) { } }
        __syncthreads();
        __threadfence();   // acquire: g_cursor visible
    }

    // scatter (seg still in registers)
    int pos = atomicAdd(&g_cursor[seg], 1);
    g_sorted[pos] = i;
    g_seg_sorted[pos] = seg;
}

// ---------------- cp.async helpers ----------------
__device__ __forceinline__ void cp_async16(uint32_t dst, const float* src) {
    asm volatile("cp.async.cg.shared.global [%0], [%1], 16;" :: "r"(dst), "l"(src));
}
__device__ __forceinline__ void cp_commit() { asm volatile("cp.async.commit_group;" ::: "memory"); }
__device__ __forceinline__ void cp_wait0() { asm volatile("cp.async.wait_group 0;" ::: "memory"); }
__device__ __forceinline__ void cp_wait1() { asm volatile("cp.async.wait_group 1;" ::: "memory"); }
__device__ __forceinline__ void cp_wait2() { asm volatile("cp.async.wait_group 2;" ::: "memory"); }

// ===== k_stream: persistent gather + grid sync + fused pass2/finalize =====
// Static smem kept at ~0; ALL scratch (ring + finalize) lives in dynamic smem
// so 3 CTAs/SM stay resident (3 x 67008 B = 201 KB <= 228 KB) -> barrier safe.
extern "C" __global__ void __launch_bounds__(TS) k_stream(const float* __restrict__ feats,
                                                          float* __restrict__ out) {
    extern __shared__ __align__(16) char sm[];
    float* ring = (float*)sm;                                  // NB*BR*ROWB = 64 KB
    int*   sidx = (int*)(sm + NB * BR * ROWB);                 // CHUNK_PAD ints
    int*   sseg = sidx + CHUNK_PAD;                            // CHUNK_PAD ints

    int bid = blockIdx.x, t = threadIdx.x;
    int c = t & 127;        // column lane: 16B at offset c*16 within each row
    int h = t >> 7;         // row parity (0/1)
    int lo = bid * CHUNK;

    for (int i = t; i < CHUNK_PAD; i += TS) {
        int gi = lo + i;
        if (i < CHUNK && gi < NROWS) {
            sidx[i] = g_sorted[gi];
            sseg[i] = g_seg_sorted[gi];
        } else {
            sidx[i] = 0;
            sseg[i] = -1;
        }
    }
    __syncthreads();

    uint32_t ring_base = (uint32_t)__cvta_generic_to_shared(ring) + (uint32_t)c * 16u;
    const float* fbase = feats + (c << 2);

    // prologue: batches 0..2 (thread loads its parity rows: 4 per batch)
    #pragma unroll
    for (int p = 0; p < 3; ++p) {
        #pragma unroll
        for (int rr = 0; rr < BR / 2; ++rr) {
            int ri = rr * 2 + h;
            const float* src = fbase + ((size_t)sidx[p * BR + ri] << 9);
            cp_async16(ring_base + (uint32_t)((p & (NB - 1)) * BR + ri) * ROWB, src);
        }
        cp_commit();
    }

    float4 acc = make_float4(0.f, 0.f, 0.f, 0.f);
    float  ssq = 0.f;
    int    cur = -1;
    int    lane = t & 31;

    for (int b = 0; b < NBATCH; ++b) {
        int k = NBATCH - 1 - b;
        if (k >= 2) cp_wait2(); else if (k == 1) cp_wait1(); else cp_wait0();

        const float* bp = ring + (size_t)((b & (NB - 1)) * BR) * DDIM + (c << 2);
        #pragma unroll
        for (int rr = 0; rr < BR / 2; ++rr) {
            int ri = rr * 2 + h;
            int sg = sseg[b * BR + ri];
            if (sg != cur) {
                if (cur >= 0) {
                    float* dst = (float*)g_sums4 + ((size_t)cur << 9) + (c << 2);
                    atomicAdd(dst + 0, acc.x);
                    atomicAdd(dst + 1, acc.y);
                    atomicAdd(dst + 2, acc.z);
                    atomicAdd(dst + 3, acc.w);
                    float ws = ssq;
                    #pragma unroll
                    for (int o = 16; o > 0; o >>= 1)
                        ws += __shfl_down_sync(0xffffffffu, ws, o);
                    if (lane == 0) atomicAdd(&g_ssq[cur], ws);
                }
                acc = make_float4(0.f, 0.f, 0.f, 0.f);
                ssq = 0.f;
                cur = sg;
            }
            if (sg >= 0) {
                float4 v = *(const float4*)(bp + (size_t)ri * DDIM);
                acc.x += v.x; acc.y += v.y; acc.z += v.z; acc.w += v.w;
                ssq += v.x * v.x + v.y * v.y + v.z * v.z + v.w * v.w;
            }
        }
        int nxt = b + 3;
        if (nxt < NBATCH) {
            #pragma unroll
            for (int rr = 0; rr < BR / 2; ++rr) {
                int ri = rr * 2 + h;
                const float* src = fbase + ((size_t)sidx[nxt * BR + ri] << 9);
                cp_async16(ring_base + (uint32_t)((nxt & (NB - 1)) * BR + ri) * ROWB, src);
            }
            cp_commit();
        }
    }
    if (cur >= 0) {
        float* dst = (float*)g_sums4 + ((size_t)cur << 9) + (c << 2);
        atomicAdd(dst + 0, acc.x);
        atomicAdd(dst + 1, acc.y);
        atomicAdd(dst + 2, acc.z);
        atomicAdd(dst + 3, acc.w);
        float ws = ssq;
        #pragma unroll
        for (int o = 16; o > 0; o >>= 1)
            ws += __shfl_down_sync(0xffffffffu, ws, o);
        if (lane == 0) atomicAdd(&g_ssq[cur], ws);
    }

    // ---- grid sync: all flushes visible (all 444 CTAs resident: one wave) ----
    __threadfence();
    __syncthreads();
    if (t == 0) {
        atomicAdd(&g_stream_done, 1);
        while (atomicAdd(&g_stream_done, 0) < GRID_STREAM) { }
    }
    __syncthreads();
    __threadfence();   // acquire

    // ---- fused pass2: one warp per group ----
    int w = t >> 5;   // 8 warps
    for (int gidx = w * GRID_STREAM + bid; gidx < NGROUP; gidx += 8 * GRID_STREAM) {
        double nn = 0.0;
        #pragma unroll
        for (int j = 0; j < 4; ++j) {
            float4 v = g_sums4[(size_t)gidx * 128 + lane + 32 * j];
            nn += (double)v.x * v.x + (double)v.y * v.y +
                  (double)v.z * v.z + (double)v.w * v.w;
        }
        #pragma unroll
        for (int o = 16; o > 0; o >>= 1)
            nn += __shfl_down_sync(0xffffffffu, nn, o);
        if (lane == 0) {
            int cnt = g_cnt[gidx];
            double den = (cnt > 0) ? (double)cnt : 1.0;
            g_gm[gidx] = ((double)g_ssq[gidx] - nn / den) / den;
        }
    }

    // ---- last-CTA finalize (scratch aliased onto the dead ring buffer) ----
    __shared__ int s_last;
    __threadfence();
    __syncthreads();
    if (t == 0)
        s_last = (atomicAdd(&g_fin_done, 1) == GRID_STREAM - 1) ? 1 : 0;
    __syncthreads();
    if (!s_last) return;
    __threadfence();

    double* fsum = (double*)sm;                    // NUM_DEMOG*TS doubles = 8 KB
    int*    fcnt = (int*)(sm + NUM_DEMOG * TS * sizeof(double));  // 4 KB

    double lsum[NUM_DEMOG] = {0.0, 0.0, 0.0, 0.0};
    int    lcnt[NUM_DEMOG] = {0, 0, 0, 0};
    for (int gg = t; gg < NGROUP; gg += TS) {
        if (g_cnt[gg] > 0) {
            int d = gg >> 9;
            lsum[d] += g_gm[gg];
            lcnt[d] += 1;
        }
    }
    #pragma unroll
    for (int d = 0; d < NUM_DEMOG; ++d) {
        fsum[d * TS + t] = lsum[d];
        fcnt[d * TS + t] = lcnt[d];
    }
    __syncthreads();
    #pragma unroll
    for (int s = TS / 2; s > 0; s >>= 1) {
        if (t < s) {
            #pragma unroll
            for (int d = 0; d < NUM_DEMOG; ++d) {
                fsum[d * TS + t] += fsum[d * TS + t + s];
                fcnt[d * TS + t] += fcnt[d * TS + t + s];
            }
        }
        __syncthreads();
    }
    if (t == 0) {
        double intra[NUM_DEMOG];
        double mu = 0.0;
        #pragma unroll
        for (int d = 0; d < NUM_DEMOG; ++d) {
            int np = fcnt[d * TS] > 0 ? fcnt[d * TS] : 1;
            intra[d] = fsum[d * TS] / (double)np;
            mu += intra[d];
        }
        mu /= (double)NUM_DEMOG;
        double loss = 0.0;
        #pragma unroll
        for (int d = 0; d < NUM_DEMOG; ++d) loss += fabs(intra[d] - mu);
        loss /= (double)NUM_DEMOG;
        out[0] = (float)loss;
    }
}

extern "C" void kernel_launch(void* const* d_in, const int* in_sizes, int n_in,
                              void* d_out, int out_size) {
    const float* feats  = (const float*)d_in[0];
    const void*  labels = d_in[1];
    const void*  demog  = d_in[2];
    float* out = (float*)d_out;

    const int smem_stream = NB * BR * ROWB + 2 * CHUNK_PAD * (int)sizeof(int) + 256;
    cudaFuncSetAttribute(k_stream, cudaFuncAttributeMaxDynamicSharedMemorySize, smem_stream);

    k_init<<<512, 512>>>((const int*)labels);
    k_prep<<<64, 1024>>>(labels, demog);
    k_stream<<<GRID_STREAM, TS, smem_stream>>>(feats, out);
}